// round 2
// baseline (speedup 1.0000x reference)
#include <cuda_runtime.h>

// ---------------- problem dims ----------------
#define BB 512
#define TT 64
#define HH 256     // hidden / obs dim
#define AA 6       // action dim
#define RR 256     // recurrent dim
#define KG 768     // 3*RR gate dim
#define LL 1024    // latent dim
#define NR 4       // rows per CTA in scan
#define NCTA 128   // BB / NR

// output layout: [deter | stoch | logits]
#define DET_OFF 0
#define ST_OFF  (BB * TT * RR)                 // 8388608
#define LG_OFF  (BB * TT * RR + BB * TT * LL)  // 41943040

// ---------------- device scratch (no allocs allowed) ----------------
__device__ __align__(16) float g_WcT[LL * KG];     // [c][k]   fused stoch weights (Wc = W_ih @ W_in)
__device__ __align__(16) float g_WcaT[AA * KG];    // [j][k]   fused action weights
__device__ __align__(16) float g_bc[KG];           // b_ih + W_ih @ b_in
__device__ __align__(16) float g_WhhT[RR * KG];    // [j][k]   W_hh transposed
__device__ __align__(16) float g_WphT[RR * LL];    // [j][l]   h-part of W_post, transposed
__device__ __align__(16) float g_WpoT[HH * LL];    // [k][n]   obs-part of W_post, transposed

// ---------------- prep 1: fuse W_ih @ [W_in | b_in] ----------------
// index: k = idx / 1031 (gate), c = idx % 1031 (0..1029 = columns, 1030 = bias)
__global__ void prep_fuse(const float* __restrict__ W_in, const float* __restrict__ b_in,
                          const float* __restrict__ W_ih, const float* __restrict__ b_ih) {
    int idx = blockIdx.x * blockDim.x + threadIdx.x;
    if (idx >= KG * 1031) return;
    int k = idx / 1031;
    int c = idx % 1031;
    float acc = 0.f;
    if (c < 1030) {
        for (int h = 0; h < HH; ++h)
            acc = fmaf(W_ih[k * HH + h], W_in[h * 1030 + c], acc);
        if (c < LL) g_WcT[c * KG + k] = acc;
        else        g_WcaT[(c - LL) * KG + k] = acc;
    } else {
        for (int h = 0; h < HH; ++h)
            acc = fmaf(W_ih[k * HH + h], b_in[h], acc);
        g_bc[k] = acc + b_ih[k];
    }
}

// ---------------- prep 2: transposes ----------------
__global__ void prep_transpose(const float* __restrict__ W_hh, const float* __restrict__ W_post) {
    int idx = blockIdx.x * blockDim.x + threadIdx.x;
    const int T1 = KG * RR;          // 196608
    const int T2 = LL * (RR + HH);   // 524288
    if (idx < T1) {
        int k = idx / RR, j = idx % RR;
        g_WhhT[j * KG + k] = W_hh[idx];
    } else if (idx < T1 + T2) {
        int e = idx - T1;
        int l = e / (RR + HH), m = e % (RR + HH);
        float v = W_post[e];
        if (m < RR) g_WphT[m * LL + l] = v;
        else        g_WpoT[(m - RR) * LL + l] = v;
    }
}

// ---------------- obs GEMM: out_logits[m][n] = b_post[n] + obs[m]·W_po[n] ----------------
// M = B*T = 32768, N = 1024, K = 256.  BM=128, BN=64, BK=16, 256 thr, 8x4 microtile.
__global__ void __launch_bounds__(256) obs_gemm(const float* __restrict__ obs,
                                                const float* __restrict__ b_post,
                                                float* __restrict__ outL) {
    __shared__ float As[128][17];
    __shared__ float Bs[16][64];
    int tid = threadIdx.x;
    int bm = blockIdx.y * 128;
    int bn = blockIdx.x * 64;
    int ty = tid >> 4;        // 0..15
    int tx = tid & 15;        // 0..15
    float acc[8][4];
    #pragma unroll
    for (int i = 0; i < 8; ++i)
        #pragma unroll
        for (int j = 0; j < 4; ++j) acc[i][j] = 0.f;

    for (int k0 = 0; k0 < HH; k0 += 16) {
        // A tile: 128x16 = 512 float4, 2 per thread
        #pragma unroll
        for (int i = 0; i < 2; ++i) {
            int f = tid + i * 256;
            int row = f >> 2;
            int kp = (f & 3) * 4;
            float4 v = *(const float4*)&obs[(size_t)(bm + row) * HH + k0 + kp];
            As[row][kp + 0] = v.x; As[row][kp + 1] = v.y;
            As[row][kp + 2] = v.z; As[row][kp + 3] = v.w;
        }
        // B tile: 16x64 = 1024 floats, 4 per thread (coalesced from g_WpoT)
        #pragma unroll
        for (int i = 0; i < 4; ++i) {
            int e = tid + i * 256;
            int kk = e >> 6;
            int n = e & 63;
            Bs[kk][n] = g_WpoT[(k0 + kk) * LL + bn + n];
        }
        __syncthreads();
        #pragma unroll
        for (int kk = 0; kk < 16; ++kk) {
            float a[8], b[4];
            #pragma unroll
            for (int i = 0; i < 8; ++i) a[i] = As[ty * 8 + i][kk];
            #pragma unroll
            for (int j = 0; j < 4; ++j) b[j] = Bs[kk][tx * 4 + j];
            #pragma unroll
            for (int i = 0; i < 8; ++i)
                #pragma unroll
                for (int j = 0; j < 4; ++j) acc[i][j] = fmaf(a[i], b[j], acc[i][j]);
        }
        __syncthreads();
    }
    float bp[4];
    #pragma unroll
    for (int j = 0; j < 4; ++j) bp[j] = b_post[bn + tx * 4 + j];
    #pragma unroll
    for (int i = 0; i < 8; ++i) {
        int m = bm + ty * 8 + i;
        float4 v;
        v.x = acc[i][0] + bp[0];
        v.y = acc[i][1] + bp[1];
        v.z = acc[i][2] + bp[2];
        v.w = acc[i][3] + bp[3];
        *(float4*)&outL[(size_t)m * LL + bn + tx * 4] = v;
    }
}

// ---------------- persistent scan ----------------
__global__ void __launch_bounds__(256, 1) scan_kernel(
    const float* __restrict__ action,
    const unsigned int* __restrict__ first,   // 4-byte nonzero test (covers f32 / i32)
    const float* __restrict__ gumbel,         // [T][B][32][32]
    const float* __restrict__ b_hh,
    float* __restrict__ out) {

    __shared__ float s_det[2][NR][RR];   // carry deter (double-buffered; [cur^1] = new h)
    __shared__ float s_gi[NR][KG];
    __shared__ float s_gh[NR][KG];
    __shared__ int   s_idx[NR][32];      // one-hot index per group
    __shared__ float s_act[NR][AA];
    __shared__ int   s_reset[NR];

    const int tid = threadIdx.x;
    const int row0 = blockIdx.x * NR;
    int cur = 0;

    for (int t = 0; t < TT; ++t) {
        // ---- per-row flags + action ----
        if (tid < NR) {
            unsigned f = first[(row0 + tid) * TT + t];
            s_reset[tid] = (t == 0) || (f != 0u);
        }
        if (tid >= 32 && tid < 32 + NR * AA) {
            int e = tid - 32;
            int r = e / AA, j = e % AA;
            s_act[r][j] = action[((size_t)(row0 + r) * TT + t) * AA + j];
        }
        __syncthreads();

        // ---- reset carry where episode starts ----
        #pragma unroll
        for (int r = 0; r < NR; ++r)
            if (s_reset[r]) s_det[cur][r][tid] = 0.f;
        __syncthreads();

        // ---- phase 1: gi / gh for all 768 gates (192 threads, k-quads) ----
        if (tid < 192) {
            const int q4 = tid * 4;
            float4 gi[NR], gh[NR];
            const float4 bc4  = *(const float4*)&g_bc[q4];
            const float4 bhh4 = *(const float4*)&b_hh[q4];
            #pragma unroll
            for (int r = 0; r < NR; ++r) { gi[r] = bc4; gh[r] = bhh4; }

            // action contribution
            #pragma unroll
            for (int j = 0; j < AA; ++j) {
                float4 w = *(const float4*)&g_WcaT[j * KG + q4];
                #pragma unroll
                for (int r = 0; r < NR; ++r) {
                    float a = s_act[r][j];
                    gi[r].x = fmaf(a, w.x, gi[r].x); gi[r].y = fmaf(a, w.y, gi[r].y);
                    gi[r].z = fmaf(a, w.z, gi[r].z); gi[r].w = fmaf(a, w.w, gi[r].w);
                }
            }
            // one-hot stoch gather
            for (int r = 0; r < NR; ++r) {
                if (!s_reset[r]) {
                    #pragma unroll 8
                    for (int g = 0; g < 32; ++g) {
                        int c = g * 32 + s_idx[r][g];
                        float4 w = *(const float4*)&g_WcT[c * KG + q4];
                        gi[r].x += w.x; gi[r].y += w.y; gi[r].z += w.z; gi[r].w += w.w;
                    }
                }
            }
            // recurrent GEMV: gh += deter · W_hhT
            #pragma unroll 4
            for (int j = 0; j < RR; ++j) {
                float4 w = *(const float4*)&g_WhhT[j * KG + q4];
                #pragma unroll
                for (int r = 0; r < NR; ++r) {
                    float d = s_det[cur][r][j];
                    gh[r].x = fmaf(d, w.x, gh[r].x); gh[r].y = fmaf(d, w.y, gh[r].y);
                    gh[r].z = fmaf(d, w.z, gh[r].z); gh[r].w = fmaf(d, w.w, gh[r].w);
                }
            }
            #pragma unroll
            for (int r = 0; r < NR; ++r) {
                *(float4*)&s_gi[r][q4] = gi[r];
                *(float4*)&s_gh[r][q4] = gh[r];
            }
        }
        __syncthreads();

        // ---- pointwise GRU cell (256 threads = units) ----
        {
            const int u = tid;
            #pragma unroll
            for (int r = 0; r < NR; ++r) {
                float ir = s_gi[r][u],        hr = s_gh[r][u];
                float iz = s_gi[r][u + 256],  hz = s_gh[r][u + 256];
                float in_ = s_gi[r][u + 512], hn = s_gh[r][u + 512];
                float rr = 1.f / (1.f + expf(-(ir + hr)));
                float z  = 1.f / (1.f + expf(-(iz + hz)));
                float n  = tanhf(fmaf(rr, hn, in_));
                float dp = s_det[cur][r][u];
                float h  = (1.f - z) * n + z * dp;
                s_det[cur ^ 1][r][u] = h;
                out[DET_OFF + ((size_t)(row0 + r) * TT + t) * RR + u] = h;
            }
        }
        __syncthreads();

        // ---- phase 2: logits += h·W_phT, argmax+gumbel, one-hot stoch ----
        {
            const int q4 = tid * 4;   // l-quad
            float4 acc[NR];
            size_t bt[NR];
            #pragma unroll
            for (int r = 0; r < NR; ++r) {
                bt[r] = (size_t)(row0 + r) * TT + t;
                acc[r] = *(const float4*)&out[LG_OFF + bt[r] * LL + q4];  // obs part + b_post
            }
            #pragma unroll 4
            for (int j = 0; j < RR; ++j) {
                float4 w = *(const float4*)&g_WphT[j * LL + q4];
                #pragma unroll
                for (int r = 0; r < NR; ++r) {
                    float h = s_det[cur ^ 1][r][j];
                    acc[r].x = fmaf(h, w.x, acc[r].x); acc[r].y = fmaf(h, w.y, acc[r].y);
                    acc[r].z = fmaf(h, w.z, acc[r].z); acc[r].w = fmaf(h, w.w, acc[r].w);
                }
            }
            #pragma unroll
            for (int r = 0; r < NR; ++r) {
                *(float4*)&out[LG_OFF + bt[r] * LL + q4] = acc[r];
                float4 g4 = *(const float4*)&gumbel[((size_t)t * BB + row0 + r) * LL + q4];
                float v0 = acc[r].x + g4.x, v1 = acc[r].y + g4.y;
                float v2 = acc[r].z + g4.z, v3 = acc[r].w + g4.w;
                // local argmax (first max wins)
                float bv = v0; int bi = q4;
                if (v1 > bv) { bv = v1; bi = q4 + 1; }
                if (v2 > bv) { bv = v2; bi = q4 + 2; }
                if (v3 > bv) { bv = v3; bi = q4 + 3; }
                // reduce across aligned 8-lane segment (one 32-wide group per segment)
                #pragma unroll
                for (int off = 1; off < 8; off <<= 1) {
                    float ov = __shfl_xor_sync(0xffffffffu, bv, off);
                    int   oi = __shfl_xor_sync(0xffffffffu, bi, off);
                    if (ov > bv || (ov == bv && oi < bi)) { bv = ov; bi = oi; }
                }
                float4 sv;
                sv.x = (q4 + 0 == bi) ? 1.f : 0.f;
                sv.y = (q4 + 1 == bi) ? 1.f : 0.f;
                sv.z = (q4 + 2 == bi) ? 1.f : 0.f;
                sv.w = (q4 + 3 == bi) ? 1.f : 0.f;
                *(float4*)&out[ST_OFF + bt[r] * LL + q4] = sv;
                if ((tid & 7) == 0) s_idx[r][tid >> 3] = bi & 31;
            }
        }
        __syncthreads();
        cur ^= 1;
    }
}

// ---------------- launcher ----------------
extern "C" void kernel_launch(void* const* d_in, const int* in_sizes, int n_in,
                              void* d_out, int out_size) {
    const float* obs          = (const float*)d_in[0];
    const float* action       = (const float*)d_in[1];
    const unsigned int* first = (const unsigned int*)d_in[2];
    const float* gumbel       = (const float*)d_in[3];
    const float* W_in         = (const float*)d_in[4];
    const float* b_in         = (const float*)d_in[5];
    const float* W_ih         = (const float*)d_in[6];
    const float* W_hh         = (const float*)d_in[7];
    const float* b_ih         = (const float*)d_in[8];
    const float* b_hh         = (const float*)d_in[9];
    const float* W_post       = (const float*)d_in[10];
    const float* b_post       = (const float*)d_in[11];
    float* out = (float*)d_out;
    (void)in_sizes; (void)n_in; (void)out_size;

    prep_fuse<<<(KG * 1031 + 255) / 256, 256>>>(W_in, b_in, W_ih, b_ih);
    prep_transpose<<<(KG * RR + LL * (RR + HH) + 255) / 256, 256>>>(W_hh, W_post);
    dim3 ggrid(LL / 64, (BB * TT) / 128);
    obs_gemm<<<ggrid, 256>>>(obs, b_post, out + LG_OFF);
    scan_kernel<<<NCTA, 256>>>(action, first, gumbel, b_hh, out);
}

// round 3
// speedup vs baseline: 1.5488x; 1.5488x over previous
#include <cuda_runtime.h>
#include <cstdint>

// ---------------- problem dims ----------------
#define BB 512
#define TT 64
#define HH 256     // hidden / obs dim
#define AA 6       // action dim
#define RR 256     // recurrent dim
#define KG 768     // 3*RR gate dim
#define LL 1024    // latent dim
#define NR 4       // rows per CTA in scan
#define NCTA 128   // BB / NR

// output layout: [deter | stoch | logits]
#define DET_OFF 0
#define ST_OFF  (BB * TT * RR)
#define LG_OFF  (BB * TT * RR + BB * TT * LL)

// ---------------- device scratch ----------------
__device__ __align__(16) float g_WcT[LL * KG];     // [c][k] fused stoch weights
__device__ __align__(16) float g_WcaT[AA * KG];    // [j][k] fused action weights
__device__ __align__(16) float g_bc[KG];           // b_ih + W_ih @ b_in
__device__ __align__(16) float g_WhhT[RR * KG];    // [j][k]
__device__ __align__(16) float g_WphT[RR * LL];    // [j][l]
__device__ __align__(16) float g_WpoT[HH * LL];    // [k][n]

// ---------------- packed fp32 helpers (FFMA2 path, PTX-only) ----------------
__device__ __forceinline__ void ffma2(float2& d, const float2 a, const float2 b) {
    asm("fma.rn.f32x2 %0, %1, %2, %0;"
        : "+l"(reinterpret_cast<unsigned long long&>(d))
        : "l"(reinterpret_cast<const unsigned long long&>(a)),
          "l"(reinterpret_cast<const unsigned long long&>(b)));
}
__device__ __forceinline__ void fadd2(float2& d, const float2 a) {
    asm("add.rn.f32x2 %0, %0, %1;"
        : "+l"(reinterpret_cast<unsigned long long&>(d))
        : "l"(reinterpret_cast<const unsigned long long&>(a)));
}

// ---------------- prep 1: fuse W_ih @ [W_in | b_in] ----------------
__global__ void prep_fuse(const float* __restrict__ W_in, const float* __restrict__ b_in,
                          const float* __restrict__ W_ih, const float* __restrict__ b_ih) {
    int idx = blockIdx.x * blockDim.x + threadIdx.x;
    if (idx >= KG * 1031) return;
    int k = idx / 1031;
    int c = idx % 1031;
    float acc = 0.f;
    if (c < 1030) {
        for (int h = 0; h < HH; ++h)
            acc = fmaf(W_ih[k * HH + h], W_in[h * 1030 + c], acc);
        if (c < LL) g_WcT[c * KG + k] = acc;
        else        g_WcaT[(c - LL) * KG + k] = acc;
    } else {
        for (int h = 0; h < HH; ++h)
            acc = fmaf(W_ih[k * HH + h], b_in[h], acc);
        g_bc[k] = acc + b_ih[k];
    }
}

// ---------------- prep 2: transposes ----------------
__global__ void prep_transpose(const float* __restrict__ W_hh, const float* __restrict__ W_post) {
    int idx = blockIdx.x * blockDim.x + threadIdx.x;
    const int T1 = KG * RR;
    const int T2 = LL * (RR + HH);
    if (idx < T1) {
        int k = idx / RR, j = idx % RR;
        g_WhhT[j * KG + k] = W_hh[idx];
    } else if (idx < T1 + T2) {
        int e = idx - T1;
        int l = e / (RR + HH), m = e % (RR + HH);
        float v = W_post[e];
        if (m < RR) g_WphT[m * LL + l] = v;
        else        g_WpoT[(m - RR) * LL + l] = v;
    }
}

// ---------------- obs GEMM (f32x2, duplicated-A broadcast) ----------------
// out_logits[m][n] = b_post[n] + obs[m]·W_po[n].  M=32768, N=1024, K=256.
__global__ void __launch_bounds__(256) obs_gemm(const float* __restrict__ obs,
                                                const float* __restrict__ b_post,
                                                float* __restrict__ outL) {
    __shared__ float2 As2[128][17];   // duplicated {a,a}
    __shared__ float  Bs[16][64];
    int tid = threadIdx.x;
    int bm = blockIdx.y * 128;
    int bn = blockIdx.x * 64;
    int ty = tid >> 4;
    int tx = tid & 15;
    float2 acc2[8][2];
    #pragma unroll
    for (int i = 0; i < 8; ++i) { acc2[i][0] = make_float2(0.f, 0.f); acc2[i][1] = make_float2(0.f, 0.f); }

    for (int k0 = 0; k0 < HH; k0 += 16) {
        #pragma unroll
        for (int i = 0; i < 2; ++i) {
            int f = tid + i * 256;
            int row = f >> 2;
            int kp = (f & 3) * 4;
            float4 v = *(const float4*)&obs[(size_t)(bm + row) * HH + k0 + kp];
            As2[row][kp + 0] = make_float2(v.x, v.x);
            As2[row][kp + 1] = make_float2(v.y, v.y);
            As2[row][kp + 2] = make_float2(v.z, v.z);
            As2[row][kp + 3] = make_float2(v.w, v.w);
        }
        #pragma unroll
        for (int i = 0; i < 4; ++i) {
            int e = tid + i * 256;
            int kk = e >> 6;
            int n = e & 63;
            Bs[kk][n] = g_WpoT[(k0 + kk) * LL + bn + n];
        }
        __syncthreads();
        #pragma unroll
        for (int kk = 0; kk < 16; ++kk) {
            float2 b0 = *(const float2*)&Bs[kk][tx * 4];
            float2 b1 = *(const float2*)&Bs[kk][tx * 4 + 2];
            #pragma unroll
            for (int i = 0; i < 8; ++i) {
                float2 a2 = As2[ty * 8 + i][kk];
                ffma2(acc2[i][0], a2, b0);
                ffma2(acc2[i][1], a2, b1);
            }
        }
        __syncthreads();
    }
    float bp0 = b_post[bn + tx * 4], bp1 = b_post[bn + tx * 4 + 1];
    float bp2 = b_post[bn + tx * 4 + 2], bp3 = b_post[bn + tx * 4 + 3];
    #pragma unroll
    for (int i = 0; i < 8; ++i) {
        int m = bm + ty * 8 + i;
        float4 v;
        v.x = acc2[i][0].x + bp0; v.y = acc2[i][0].y + bp1;
        v.z = acc2[i][1].x + bp2; v.w = acc2[i][1].y + bp3;
        *(float4*)&outL[(size_t)m * LL + bn + tx * 4] = v;
    }
}

// ---------------- persistent scan: 512 threads, j-split halves, f32x2 ----------------
__global__ void __launch_bounds__(512, 1) scan_kernel(
    const float* __restrict__ action,
    const unsigned int* __restrict__ first,
    const float* __restrict__ gumbel,       // [T][B][1024]
    const float* __restrict__ b_hh,
    float* __restrict__ out) {

    // pool holds gi|gh partials (24 KB); aliased by phase-2 logits partials (16 KB)
    __shared__ __align__(16) float  s_pool[NR * KG * 2];
    __shared__ __align__(16) float2 s_det2[2][NR][RR];   // duplicated {h,h}
    __shared__ int   s_idx[NR][32];
    __shared__ float s_act[NR][AA];
    __shared__ int   s_reset[NR];

    float (*s_gi)[KG] = (float(*)[KG])s_pool;
    float (*s_gh)[KG] = (float(*)[KG])(s_pool + NR * KG);
    float (*s_lg)[LL] = (float(*)[LL])s_pool;

    const int tid = threadIdx.x;
    const int jh  = tid >> 8;      // j-half 0/1
    const int lk  = tid & 255;
    const int row0 = blockIdx.x * NR;
    int cur = 0;

    for (int t = 0; t < TT; ++t) {
        // ---- flags + action ----
        if (tid < NR) {
            unsigned f = first[(row0 + tid) * TT + t];
            s_reset[tid] = (t == 0) || (f != 0u);
        }
        if (tid >= 32 && tid < 32 + NR * AA) {
            int e = tid - 32;
            s_act[e / AA][e % AA] = action[((size_t)(row0 + e / AA) * TT + t) * AA + (e % AA)];
        }
        __syncthreads();

        // ---- zero carry on reset (each half zeroes its 2 rows) ----
        {
            int r0 = jh * 2, r1 = r0 + 1;
            if (s_reset[r0]) s_det2[cur][r0][lk] = make_float2(0.f, 0.f);
            if (s_reset[r1]) s_det2[cur][r1][lk] = make_float2(0.f, 0.f);
        }
        __syncthreads();

        // ---- phase 1: gi/gh partials (j-split). regs persist across syncs ----
        float2 gi[NR][2], gh[NR][2];
        if (lk < 192) {
            const int q4 = lk * 4;
            if (jh == 0) {
                float4 bc = *(const float4*)&g_bc[q4];
                float4 bh = *(const float4*)&b_hh[q4];
                #pragma unroll
                for (int r = 0; r < NR; ++r) {
                    gi[r][0] = make_float2(bc.x, bc.y); gi[r][1] = make_float2(bc.z, bc.w);
                    gh[r][0] = make_float2(bh.x, bh.y); gh[r][1] = make_float2(bh.z, bh.w);
                }
            } else {
                #pragma unroll
                for (int r = 0; r < NR; ++r) {
                    gi[r][0] = make_float2(0.f, 0.f); gi[r][1] = make_float2(0.f, 0.f);
                    gh[r][0] = make_float2(0.f, 0.f); gh[r][1] = make_float2(0.f, 0.f);
                }
                // action contribution (jh1 only)
                #pragma unroll
                for (int j = 0; j < AA; ++j) {
                    float4 w = *(const float4*)&g_WcaT[j * KG + q4];
                    float2 wl = make_float2(w.x, w.y), wh2 = make_float2(w.z, w.w);
                    #pragma unroll
                    for (int r = 0; r < NR; ++r) {
                        float a = s_act[r][j];
                        ffma2(gi[r][0], make_float2(a, a), wl);
                        ffma2(gi[r][1], make_float2(a, a), wh2);
                    }
                }
            }
            // one-hot gather: each half handles its own 2 rows
            #pragma unroll
            for (int rr2 = 0; rr2 < 2; ++rr2) {
                int r = jh * 2 + rr2;
                if (!s_reset[r]) {
                    #pragma unroll 8
                    for (int g = 0; g < 32; ++g) {
                        int c = (g << 5) + s_idx[r][g];
                        float4 w = *(const float4*)&g_WcT[c * KG + q4];
                        fadd2(gi[r][0], make_float2(w.x, w.y));
                        fadd2(gi[r][1], make_float2(w.z, w.w));
                    }
                }
            }
            // recurrent GEMV over this thread's j-half
            const float* wb = &g_WhhT[(jh * 128) * KG + q4];
            #pragma unroll 8
            for (int jj = 0; jj < 128; ++jj) {
                float4 w = *(const float4*)(wb + (size_t)jj * KG);
                float2 wl = make_float2(w.x, w.y), wh2 = make_float2(w.z, w.w);
                int j = jh * 128 + jj;
                #pragma unroll
                for (int r = 0; r < NR; ++r) {
                    float2 d2 = s_det2[cur][r][j];
                    ffma2(gh[r][0], d2, wl);
                    ffma2(gh[r][1], d2, wh2);
                }
            }
            if (jh == 0) {
                #pragma unroll
                for (int r = 0; r < NR; ++r) {
                    *(float2*)&s_gi[r][q4]     = gi[r][0];
                    *(float2*)&s_gi[r][q4 + 2] = gi[r][1];
                    *(float2*)&s_gh[r][q4]     = gh[r][0];
                    *(float2*)&s_gh[r][q4 + 2] = gh[r][1];
                }
            }
        }
        __syncthreads();
        if (jh == 1 && lk < 192) {     // add jh1 partial in place
            const int q4 = lk * 4;
            #pragma unroll
            for (int r = 0; r < NR; ++r) {
                float2 a0 = *(float2*)&s_gi[r][q4],     a1 = *(float2*)&s_gi[r][q4 + 2];
                float2 b0 = *(float2*)&s_gh[r][q4],     b1 = *(float2*)&s_gh[r][q4 + 2];
                fadd2(a0, gi[r][0]); fadd2(a1, gi[r][1]);
                fadd2(b0, gh[r][0]); fadd2(b1, gh[r][1]);
                *(float2*)&s_gi[r][q4] = a0;     *(float2*)&s_gi[r][q4 + 2] = a1;
                *(float2*)&s_gh[r][q4] = b0;     *(float2*)&s_gh[r][q4 + 2] = b1;
            }
        }
        __syncthreads();

        // ---- GRU pointwise: u = lk, each half does its 2 rows ----
        {
            const int u = lk;
            #pragma unroll
            for (int rr2 = 0; rr2 < 2; ++rr2) {
                int r = jh * 2 + rr2;
                float ir = s_gi[r][u],       hr = s_gh[r][u];
                float iz = s_gi[r][u + 256], hz = s_gh[r][u + 256];
                float in_ = s_gi[r][u + 512], hn = s_gh[r][u + 512];
                float rg = 1.f / (1.f + expf(-(ir + hr)));
                float z  = 1.f / (1.f + expf(-(iz + hz)));
                float n  = tanhf(fmaf(rg, hn, in_));
                float dp = s_det2[cur][r][u].x;
                float h  = (1.f - z) * n + z * dp;
                s_det2[cur ^ 1][r][u] = make_float2(h, h);
                out[DET_OFF + ((size_t)(row0 + r) * TT + t) * RR + u] = h;
            }
        }
        __syncthreads();

        // ---- phase 2: logits partials (j-split over h) ----
        float2 acc[NR][2];
        {
            const int q4 = lk * 4;
            if (jh == 0) {
                #pragma unroll
                for (int r = 0; r < NR; ++r) {
                    size_t bt = (size_t)(row0 + r) * TT + t;
                    float4 v = *(const float4*)&out[LG_OFF + bt * LL + q4]; // obs part + b_post
                    acc[r][0] = make_float2(v.x, v.y); acc[r][1] = make_float2(v.z, v.w);
                }
            } else {
                #pragma unroll
                for (int r = 0; r < NR; ++r) {
                    acc[r][0] = make_float2(0.f, 0.f); acc[r][1] = make_float2(0.f, 0.f);
                }
            }
            const float* wb = &g_WphT[(jh * 128) * LL + q4];
            #pragma unroll 8
            for (int jj = 0; jj < 128; ++jj) {
                float4 w = *(const float4*)(wb + (size_t)jj * LL);
                float2 wl = make_float2(w.x, w.y), wh2 = make_float2(w.z, w.w);
                int j = jh * 128 + jj;
                #pragma unroll
                for (int r = 0; r < NR; ++r) {
                    float2 h2 = s_det2[cur ^ 1][r][j];
                    ffma2(acc[r][0], h2, wl);
                    ffma2(acc[r][1], h2, wh2);
                }
            }
            if (jh == 0) {    // stash partial in s_lg (aliases gi/gh pool — consumed)
                #pragma unroll
                for (int r = 0; r < NR; ++r) {
                    *(float2*)&s_lg[r][q4]     = acc[r][0];
                    *(float2*)&s_lg[r][q4 + 2] = acc[r][1];
                }
            }
        }
        __syncthreads();

        // ---- combine + argmax + one-hot (jh1 threads only) ----
        if (jh == 1) {
            const int q4 = lk * 4;
            #pragma unroll
            for (int r = 0; r < NR; ++r) {
                size_t bt = (size_t)(row0 + r) * TT + t;
                float4 p = *(const float4*)&s_lg[r][q4];
                float4 lg;
                lg.x = acc[r][0].x + p.x; lg.y = acc[r][0].y + p.y;
                lg.z = acc[r][1].x + p.z; lg.w = acc[r][1].y + p.w;
                *(float4*)&out[LG_OFF + bt * LL + q4] = lg;
                float4 g4 = *(const float4*)&gumbel[((size_t)t * BB + row0 + r) * LL + q4];
                float v0 = lg.x + g4.x, v1 = lg.y + g4.y;
                float v2 = lg.z + g4.z, v3 = lg.w + g4.w;
                float bv = v0; int bi = q4;
                if (v1 > bv) { bv = v1; bi = q4 + 1; }
                if (v2 > bv) { bv = v2; bi = q4 + 2; }
                if (v3 > bv) { bv = v3; bi = q4 + 3; }
                #pragma unroll
                for (int off = 1; off < 8; off <<= 1) {
                    float ov = __shfl_xor_sync(0xffffffffu, bv, off);
                    int   oi = __shfl_xor_sync(0xffffffffu, bi, off);
                    if (ov > bv || (ov == bv && oi < bi)) { bv = ov; bi = oi; }
                }
                float4 sv;
                sv.x = (q4 + 0 == bi) ? 1.f : 0.f;
                sv.y = (q4 + 1 == bi) ? 1.f : 0.f;
                sv.z = (q4 + 2 == bi) ? 1.f : 0.f;
                sv.w = (q4 + 3 == bi) ? 1.f : 0.f;
                *(float4*)&out[ST_OFF + bt * LL + q4] = sv;
                if ((lk & 7) == 0) s_idx[r][lk >> 3] = bi & 31;
            }
        }
        __syncthreads();
        cur ^= 1;
    }
}

// ---------------- launcher ----------------
extern "C" void kernel_launch(void* const* d_in, const int* in_sizes, int n_in,
                              void* d_out, int out_size) {
    const float* obs          = (const float*)d_in[0];
    const float* action       = (const float*)d_in[1];
    const unsigned int* first = (const unsigned int*)d_in[2];
    const float* gumbel       = (const float*)d_in[3];
    const float* W_in         = (const float*)d_in[4];
    const float* b_in         = (const float*)d_in[5];
    const float* W_ih         = (const float*)d_in[6];
    const float* W_hh         = (const float*)d_in[7];
    const float* b_ih         = (const float*)d_in[8];
    const float* b_hh         = (const float*)d_in[9];
    const float* W_post       = (const float*)d_in[10];
    const float* b_post       = (const float*)d_in[11];
    float* out = (float*)d_out;
    (void)in_sizes; (void)n_in; (void)out_size;

    prep_fuse<<<(KG * 1031 + 255) / 256, 256>>>(W_in, b_in, W_ih, b_ih);
    prep_transpose<<<(KG * RR + LL * (RR + HH) + 255) / 256, 256>>>(W_hh, W_post);
    dim3 ggrid(LL / 64, (BB * TT) / 128);
    obs_gemm<<<ggrid, 256>>>(obs, b_post, out + LG_OFF);
    scan_kernel<<<NCTA, 512>>>(action, first, gumbel, b_hh, out);
}